// round 2
// baseline (speedup 1.0000x reference)
#include <cuda_runtime.h>
#include <cstdint>
#include <cstddef>

// Problem constants (fixed by the dataset)
#define N_TOT 131072   // B*S = 128*1024 points
#define D_DIM 256      // feature dim
#define K_CL  512      // clusters

// Tiling for the fused GEMM+argmin kernel
#define MT 128         // points per CTA
#define KT 128         // clusters per k-tile
#define TD 16          // D-chunk held in smem

// Near-tie threshold: fast-path fp32 error is ~1e-5 RMS; τ = 1/64 is ~1000σ.
#define TAU 0.015625f

// Scratch (device globals — no allocation allowed)
__device__ int   g_idx[N_TOT];
__device__ float g_sums[K_CL * D_DIM];
__device__ int   g_counts[K_CL];
__device__ float g_c2[K_CL];
__device__ int   g_nref;
__device__ int   g_rlist[N_TOT];

__device__ __forceinline__ unsigned long long pack_dup(float v) {
    unsigned u = __float_as_uint(v);
    return ((unsigned long long)u << 32) | (unsigned long long)u;
}

// packed f32x2 FMA: acc.lo += a.lo*b.lo ; acc.hi += a.hi*b.hi
#define FMA2(acc, a, b) asm("fma.rn.f32x2 %0, %1, %2, %0;" : "+l"(acc) : "l"(a), "l"(b))

// ---------------------------------------------------------------------------
// init: zero sums/counts/refine-counter, c2[k] = sum_d C[k][d]^2 (fp64 -> fp32)
// ---------------------------------------------------------------------------
__global__ void init_kernel(const float* __restrict__ C) {
    int t = blockIdx.x * blockDim.x + threadIdx.x;
    if (t == 0) g_nref = 0;
    if (t < K_CL * D_DIM) g_sums[t] = 0.0f;
    if (t < K_CL) {
        g_counts[t] = 0;
        const float4* c = (const float4*)(C + (size_t)t * D_DIM);
        double s = 0.0;
        #pragma unroll
        for (int j = 0; j < D_DIM / 4; ++j) {
            float4 v = c[j];
            s += (double)v.x * v.x + (double)v.y * v.y
               + (double)v.z * v.z + (double)v.w * v.w;
        }
        g_c2[t] = (float)s;
    }
}

// ---------------------------------------------------------------------------
// fused distance-GEMM + argmin with best/second-best tracking.
// score(n,k) = c2(k) - 2 x.c  (x2 drops out of the argmin).
// Confident points (gap >= TAU) get their one-hot written here; near-ties are
// appended to g_rlist for exact refinement.
// ---------------------------------------------------------------------------
__global__ __launch_bounds__(256, 2)
void argmin_kernel(const float* __restrict__ X, const float* __restrict__ C,
                   float* __restrict__ out) {
    __shared__ float xs[TD][MT];                 // x chunk, transposed: xs[d][p]
    __shared__ unsigned long long csp[TD][KT];   // centroid chunk, value duplicated (v,v)
    __shared__ float c2s[KT];

    const int tid = threadIdx.x;
    const int tx = tid & 15;    // cluster-group lane (16)
    const int ty = tid >> 4;    // point-group (16) -> 8 points each
    const int n0 = blockIdx.x * MT;

    const int lrow = tid & 127; // row for cooperative loads
    const int dg   = tid >> 7;  // 0/1: which 8-dim half of the chunk

    float best[8], best2[8];
    int   bidx[8];
    #pragma unroll
    for (int i = 0; i < 8; ++i) { best[i] = 3.4e38f; best2[i] = 3.4e38f; bidx[i] = 0; }

    for (int kt = 0; kt < K_CL; kt += KT) {
        __syncthreads();                     // protect c2s/smem from prior iteration
        if (tid < KT) c2s[tid] = g_c2[kt + tid];

        unsigned long long acc[8][4];        // [cluster][point-pair], f32x2 packed
        #pragma unroll
        for (int kk = 0; kk < 8; ++kk)
            #pragma unroll
            for (int pp = 0; pp < 4; ++pp) acc[kk][pp] = 0ull;

        for (int dt = 0; dt < D_DIM; dt += TD) {
            __syncthreads();
            {   // cooperative load of x chunk (transpose) and centroid chunk (dup-pack)
                const float* xsrc = X + (size_t)(n0 + lrow) * D_DIM + dt + dg * 8;
                float4 a = *(const float4*)xsrc;
                float4 b = *(const float4*)(xsrc + 4);
                int db = dg * 8;
                xs[db + 0][lrow] = a.x; xs[db + 1][lrow] = a.y;
                xs[db + 2][lrow] = a.z; xs[db + 3][lrow] = a.w;
                xs[db + 4][lrow] = b.x; xs[db + 5][lrow] = b.y;
                xs[db + 6][lrow] = b.z; xs[db + 7][lrow] = b.w;

                const float* csrc = C + (size_t)(kt + lrow) * D_DIM + dt + dg * 8;
                float4 ca = *(const float4*)csrc;
                float4 cb = *(const float4*)(csrc + 4);
                csp[db + 0][lrow] = pack_dup(ca.x); csp[db + 1][lrow] = pack_dup(ca.y);
                csp[db + 2][lrow] = pack_dup(ca.z); csp[db + 3][lrow] = pack_dup(ca.w);
                csp[db + 4][lrow] = pack_dup(cb.x); csp[db + 5][lrow] = pack_dup(cb.y);
                csp[db + 6][lrow] = pack_dup(cb.z); csp[db + 7][lrow] = pack_dup(cb.w);
            }
            __syncthreads();

            #pragma unroll
            for (int d = 0; d < TD; ++d) {
                ulonglong2 x01 = *(const ulonglong2*)&xs[d][ty * 8];
                ulonglong2 x23 = *(const ulonglong2*)&xs[d][ty * 8 + 4];
                unsigned long long xp[4] = { x01.x, x01.y, x23.x, x23.y };
                ulonglong2 c0 = *(const ulonglong2*)&csp[d][tx * 8 + 0];
                ulonglong2 c1 = *(const ulonglong2*)&csp[d][tx * 8 + 2];
                ulonglong2 c2 = *(const ulonglong2*)&csp[d][tx * 8 + 4];
                ulonglong2 c3 = *(const ulonglong2*)&csp[d][tx * 8 + 6];
                unsigned long long cc[8] = { c0.x, c0.y, c1.x, c1.y,
                                             c2.x, c2.y, c3.x, c3.y };
                #pragma unroll
                for (int kk = 0; kk < 8; ++kk)
                    #pragma unroll
                    for (int pp = 0; pp < 4; ++pp)
                        FMA2(acc[kk][pp], cc[kk], xp[pp]);
            }
        }

        // epilogue: score = c2[k] - 2*dot, running top-2 (tie -> lower k)
        #pragma unroll
        for (int kk = 0; kk < 8; ++kk) {
            int k = kt + tx * 8 + kk;
            float c2val = c2s[tx * 8 + kk];
            #pragma unroll
            for (int pp = 0; pp < 4; ++pp) {
                unsigned long long a = acc[kk][pp];
                float lo = __uint_as_float((unsigned)a);
                float hi = __uint_as_float((unsigned)(a >> 32));
                float slo = fmaf(-2.0f, lo, c2val);
                float shi = fmaf(-2.0f, hi, c2val);
                int p0 = pp * 2, p1 = pp * 2 + 1;
                if (slo < best[p0]) { best2[p0] = best[p0]; best[p0] = slo; bidx[p0] = k; }
                else if (slo < best2[p0]) { best2[p0] = slo; }
                if (shi < best[p1]) { best2[p1] = best[p1]; best[p1] = shi; bidx[p1] = k; }
                else if (shi < best2[p1]) { best2[p1] = shi; }
            }
        }
    }

    // cross-lane top-2 merge over the 16 tx lanes (contiguous tids, same half-warp)
    #pragma unroll
    for (int p = 0; p < 8; ++p) {
        float v = best[p], s = best2[p];
        int   i = bidx[p];
        #pragma unroll
        for (int o = 8; o >= 1; o >>= 1) {
            float v2 = __shfl_xor_sync(0xFFFFFFFFu, v, o);
            int   i2 = __shfl_xor_sync(0xFFFFFFFFu, i, o);
            float s2 = __shfl_xor_sync(0xFFFFFFFFu, s, o);
            if (v2 < v || (v2 == v && i2 < i)) {
                s = fminf(v, s2); v = v2; i = i2;
            } else {
                s = fminf(s, v2);
            }
        }
        if (tx == 0) {
            int n = n0 + ty * 8 + p;
            g_idx[n] = i;
            if (s - v >= TAU) {
                out[(size_t)n * K_CL + i] = 1.0f;   // rest already zeroed by memset
            } else {
                int slot = atomicAdd(&g_nref, 1);
                g_rlist[slot] = n;                  // exact pass decides this point
            }
        }
    }
}

// ---------------------------------------------------------------------------
// refine: for near-tie points, compute all K distances near-exactly (Kahan fp32
// dot, err ~1e-6 abs) and assemble dist with the reference's rounding order:
//   fl( fl(x2 - 2*dot) + c2 ),  argmin with first-index tie-break.
// ---------------------------------------------------------------------------
__device__ __forceinline__ void kadd(float& s, float& comp, float t) {
    float y = __fsub_rn(t, comp);
    float u = __fadd_rn(s, y);
    comp = __fsub_rn(__fsub_rn(u, s), y);
    s = u;
}

__global__ __launch_bounds__(256)
void refine_kernel(const float* __restrict__ X, const float* __restrict__ C,
                   float* __restrict__ out) {
    __shared__ float  xsh[D_DIM];
    __shared__ double xwr[8];
    __shared__ float  x2sh;
    __shared__ float  rv[256];
    __shared__ int    ri[256];

    const int tid  = threadIdx.x;
    const int nref = g_nref;

    for (int it = blockIdx.x; it < nref; it += gridDim.x) {
        const int n = g_rlist[it];
        __syncthreads();     // smem reuse guard across iterations
        xsh[tid] = X[(size_t)n * D_DIM + tid];
        __syncthreads();

        // x2 in fp64 -> fp32
        {
            double p = (double)xsh[tid] * (double)xsh[tid];
            #pragma unroll
            for (int o = 16; o >= 1; o >>= 1)
                p += __shfl_xor_sync(0xFFFFFFFFu, p, o);
            if ((tid & 31) == 0) xwr[tid >> 5] = p;
            __syncthreads();
            if (tid == 0) {
                double t = 0.0;
                #pragma unroll
                for (int w = 0; w < 8; ++w) t += xwr[w];
                x2sh = (float)t;
            }
            __syncthreads();
        }
        const float x2f = x2sh;
        const float4* xs4 = (const float4*)xsh;

        float bv = 3.4e38f;
        int   bi = 0x7fffffff;
        #pragma unroll
        for (int kk = 0; kk < 2; ++kk) {
            const int k = 2 * tid + kk;
            const float4* cp = (const float4*)(C + (size_t)k * D_DIM);
            float s = 0.0f, comp = 0.0f;
            #pragma unroll 4
            for (int j = 0; j < D_DIM / 4; ++j) {
                float4 cv = cp[j];
                float4 xv = xs4[j];
                kadd(s, comp, __fmul_rn(cv.x, xv.x));
                kadd(s, comp, __fmul_rn(cv.y, xv.y));
                kadd(s, comp, __fmul_rn(cv.z, xv.z));
                kadd(s, comp, __fmul_rn(cv.w, xv.w));
            }
            float dotf = __fadd_rn(s, comp);
            // reference rounding order: ((x2 - 2*xc) + c2)
            float m = __fmul_rn(2.0f, dotf);
            float a = __fsub_rn(x2f, m);
            float dist = __fadd_rn(a, g_c2[k]);
            if (dist < bv || (dist == bv && k < bi)) { bv = dist; bi = k; }
        }

        rv[tid] = bv; ri[tid] = bi;
        __syncthreads();
        #pragma unroll
        for (int st = 128; st > 0; st >>= 1) {
            if (tid < st) {
                float ov = rv[tid + st]; int oi = ri[tid + st];
                if (ov < rv[tid] || (ov == rv[tid] && oi < ri[tid])) {
                    rv[tid] = ov; ri[tid] = oi;
                }
            }
            __syncthreads();
        }
        if (tid == 0) {
            g_idx[n] = ri[0];
            out[(size_t)n * K_CL + ri[0]] = 1.0f;
        }
    }
}

// ---------------------------------------------------------------------------
// scatter-reduce points into per-cluster sums + counts (one warp per point)
// ---------------------------------------------------------------------------
__global__ void accum_kernel(const float* __restrict__ X) {
    int gw   = (blockIdx.x * blockDim.x + threadIdx.x) >> 5;
    int lane = threadIdx.x & 31;
    if (gw >= N_TOT) return;
    int k = g_idx[gw];
    const float* x = X + (size_t)gw * D_DIM;
    float* s = g_sums + (size_t)k * D_DIM;
    #pragma unroll
    for (int j = 0; j < D_DIM / 32; ++j) {
        int d = lane + j * 32;
        atomicAdd(&s[d], x[d]);
    }
    if (lane == 0) atomicAdd(&g_counts[k], 1);
}

// ---------------------------------------------------------------------------
// EMA centroid update into d_out tail
// ---------------------------------------------------------------------------
__global__ void finalize_kernel(const float* __restrict__ C, float* __restrict__ outc) {
    int t = blockIdx.x * blockDim.x + threadIdx.x;
    if (t >= K_CL * D_DIM) return;
    int k = t >> 8; // / D_DIM
    float cnt = (float)g_counts[k];
    float nc  = g_sums[t] / cnt;
    outc[t] = fmaf(0.9f, C[t], 0.1f * nc);
}

// ---------------------------------------------------------------------------
extern "C" void kernel_launch(void* const* d_in, const int* in_sizes, int n_in,
                              void* d_out, int out_size) {
    const float* X = (const float*)d_in[0];   // inputs [128,1024,256] f32
    const float* C = (const float*)d_in[1];   // centroids [512,256] f32
    float* out = (float*)d_out;               // [N*K one-hot | K*D centroids]

    (void)in_sizes; (void)n_in; (void)out_size;

    cudaMemsetAsync(out, 0, (size_t)N_TOT * K_CL * sizeof(float), 0);
    init_kernel<<<(K_CL * D_DIM + 255) / 256, 256>>>(C);
    argmin_kernel<<<N_TOT / MT, 256>>>(X, C, out);
    refine_kernel<<<512, 256>>>(X, C, out);
    accum_kernel<<<(N_TOT * 32) / 256, 256>>>(X);
    finalize_kernel<<<(K_CL * D_DIM + 255) / 256, 256>>>(C, out + (size_t)N_TOT * K_CL);
}

// round 4
// speedup vs baseline: 2.0177x; 2.0177x over previous
#include <cuda_runtime.h>
#include <cstdint>
#include <cstddef>

// Problem constants
#define N_TOT 131072   // B*S points
#define D_DIM 256      // feature dim
#define K_CL  512      // clusters

#define MT 128         // points per CTA tile
// tf32 fast-path near-tie threshold (score err-diff RMS ~0.03 -> >12 sigma)
#define TAU 0.4f

// ---- dynamic SMEM layout (bytes) ----
// X tile: [128][260] f32 (stride 260 for conflict-free A-frag LDS)
#define XSTR 260
#define SM_X   0
#define SM_B0  133120                 // C chunk buf0: [128][68] f32
#define SM_B1  (SM_B0 + 34816)
#define SM_C2  (SM_B1 + 34816)        // 512 f32
#define SM_BV  (SM_C2 + 2048)         // float[4][128]
#define SM_SV  (SM_BV + 2048)         // float[4][128]
#define SM_IV  (SM_SV + 2048)         // int  [4][128]
#define SMEM_TOTAL (SM_IV + 2048)     // 210944
#define BSTR 68

// Scratch (device globals — no allocation allowed)
__device__ int   g_idx[N_TOT];
__device__ float g_sums[K_CL * D_DIM];
__device__ int   g_counts[K_CL];
__device__ float g_c2[K_CL];
__device__ int   g_nref;
__device__ int   g_rlist[N_TOT];

// ---------------- portable PTX helpers (NO 'a'-gated features) -------------
__device__ __forceinline__ uint32_t smem_u32(const void* p) {
    uint32_t a;
    asm("{ .reg .u64 t; cvta.to.shared.u64 t, %1; cvt.u32.u64 %0, t; }"
        : "=r"(a) : "l"(p));
    return a;
}
__device__ __forceinline__ void cpa16(uint32_t dst, const void* src) {
    asm volatile("cp.async.cg.shared.global [%0], [%1], 16;"
                 :: "r"(dst), "l"(src) : "memory");
}
#define CP_COMMIT() asm volatile("cp.async.commit_group;" ::: "memory")
#define CP_WAIT(n)  asm volatile("cp.async.wait_group %0;" :: "n"(n) : "memory")

__device__ __forceinline__ uint32_t f2tf(float f) {
    uint32_t r;
    asm("cvt.rna.tf32.f32 %0, %1;" : "=r"(r) : "f"(f));
    return r;
}
__device__ __forceinline__ void mma8(float* d, const uint32_t* a, const uint32_t* b) {
    asm volatile(
        "mma.sync.aligned.m16n8k8.row.col.f32.tf32.tf32.f32 "
        "{%0,%1,%2,%3}, {%4,%5,%6,%7}, {%8,%9}, {%0,%1,%2,%3};"
        : "+f"(d[0]), "+f"(d[1]), "+f"(d[2]), "+f"(d[3])
        : "r"(a[0]), "r"(a[1]), "r"(a[2]), "r"(a[3]), "r"(b[0]), "r"(b[1]));
}

// ---------------------------------------------------------------------------
// init: zero refine-counter/sums/counts, c2[k] = sum_d C[k][d]^2 (fp64->fp32)
// ---------------------------------------------------------------------------
__global__ void init_kernel(const float* __restrict__ C) {
    int t = blockIdx.x * blockDim.x + threadIdx.x;
    if (t == 0) g_nref = 0;
    if (t < K_CL * D_DIM) g_sums[t] = 0.0f;
    if (t < K_CL) {
        g_counts[t] = 0;
        const float4* c = (const float4*)(C + (size_t)t * D_DIM);
        double s = 0.0;
        #pragma unroll
        for (int j = 0; j < D_DIM / 4; ++j) {
            float4 v = c[j];
            s += (double)v.x * v.x + (double)v.y * v.y
               + (double)v.z * v.z + (double)v.w * v.w;
        }
        g_c2[t] = (float)s;
    }
}

// ---------------------------------------------------------------------------
// C chunk loader: C[kt .. kt+128)[dbase .. dbase+64) -> smem [128][BSTR]
// ---------------------------------------------------------------------------
__device__ __forceinline__ void load_cchunk(const float* __restrict__ C,
                                            uint32_t base, int kt, int dbase,
                                            int tid) {
    #pragma unroll
    for (int i = 0; i < 8; ++i) {
        int idx = i * 256 + tid;
        int r = idx >> 4, s = idx & 15;
        cpa16(base + r * (BSTR * 4) + s * 16,
              C + (size_t)(kt + r) * D_DIM + dbase + s * 4);
    }
}

// ---------------------------------------------------------------------------
// mma.sync tf32 fused distance-GEMM + argmin (top-2) per 128-point tile.
// Streams each point's full one-hot row (no separate memset).
// ---------------------------------------------------------------------------
__global__ __launch_bounds__(256, 1)
void argmin_mma(const float* __restrict__ X, const float* __restrict__ C,
                float* __restrict__ out) {
    extern __shared__ char smem[];
    const uint32_t sb = smem_u32(smem);
    const int tid  = threadIdx.x;
    const int wid  = tid >> 5, lane = tid & 31;
    const int qrow = lane >> 2, qcol = lane & 3;
    const int wm   = wid & 1,  wn   = wid >> 1;   // 2m x 4n warp grid
    const int RM   = wm * 64,  CN   = wn * 32;
    const int n0   = blockIdx.x * MT;

    float*      Xs  = (float*)(smem + SM_X);
    float*      c2s = (float*)(smem + SM_C2);
    float*      bvS = (float*)(smem + SM_BV);
    float*      svS = (float*)(smem + SM_SV);
    int*        ivS = (int*)  (smem + SM_IV);

    // stage c2
    c2s[tid]       = g_c2[tid];
    c2s[tid + 256] = g_c2[tid + 256];

    // X tile load (one cp.async group)
    #pragma unroll
    for (int i = 0; i < 32; ++i) {
        int idx = i * 256 + tid;
        int r = idx >> 6, s = idx & 63;
        cpa16(sb + SM_X + r * (XSTR * 4) + s * 16,
              X + (size_t)(n0 + r) * D_DIM + s * 4);
    }
    CP_COMMIT();
    load_cchunk(C, sb + SM_B0, 0, 0, tid);  CP_COMMIT();
    load_cchunk(C, sb + SM_B1, 0, 64, tid); CP_COMMIT();
    CP_WAIT(1);           // X + chunk0 ready
    __syncthreads();

    float acc[4][4][4];
    #pragma unroll
    for (int a = 0; a < 4; ++a)
        #pragma unroll
        for (int b = 0; b < 4; ++b)
            #pragma unroll
            for (int c = 0; c < 4; ++c) acc[a][b][c] = 0.0f;

    float best[8], sec[8];
    int   idx8[8];
    #pragma unroll
    for (int t = 0; t < 8; ++t) { best[t] = 3.4e38f; sec[t] = 3.4e38f; idx8[t] = 0; }

    for (int q = 0; q < 16; ++q) {
        const int sbuf  = q & 1;
        const int kt    = (q >> 2) * 128;
        const int dbase = (q & 3) * 64;
        const float* Bs = (const float*)(smem + (sbuf ? SM_B1 : SM_B0));

        #pragma unroll
        for (int ks = 0; ks < 8; ++ks) {
            const int dX = dbase + ks * 8 + qcol;
            uint32_t Af[4][4];
            #pragma unroll
            for (int mt = 0; mt < 4; ++mt) {
                int r = RM + mt * 16 + qrow;
                Af[mt][0] = f2tf(Xs[r * XSTR + dX]);
                Af[mt][1] = f2tf(Xs[(r + 8) * XSTR + dX]);
                Af[mt][2] = f2tf(Xs[r * XSTR + dX + 4]);
                Af[mt][3] = f2tf(Xs[(r + 8) * XSTR + dX + 4]);
            }
            uint32_t Bf[4][2];
            #pragma unroll
            for (int nt = 0; nt < 4; ++nt) {
                int n = CN + nt * 8 + qrow;
                Bf[nt][0] = f2tf(Bs[n * BSTR + ks * 8 + qcol]);
                Bf[nt][1] = f2tf(Bs[n * BSTR + ks * 8 + 4 + qcol]);
            }
            #pragma unroll
            for (int mt = 0; mt < 4; ++mt)
                #pragma unroll
                for (int nt = 0; nt < 4; ++nt)
                    mma8(acc[mt][nt], Af[mt], Bf[nt]);
        }

        if ((q & 3) == 3) {
            // pass epilogue: score = c2 - 2*dot, update per-slot top-2, zero acc
            #pragma unroll
            for (int mt = 0; mt < 4; ++mt) {
                #pragma unroll
                for (int nt = 0; nt < 4; ++nt) {
                    int k0 = kt + CN + nt * 8 + 2 * qcol;
                    float c20 = c2s[k0], c21 = c2s[k0 + 1];
                    float s0 = fmaf(-2.0f, acc[mt][nt][0], c20);
                    float s1 = fmaf(-2.0f, acc[mt][nt][1], c21);
                    float s2 = fmaf(-2.0f, acc[mt][nt][2], c20);
                    float s3 = fmaf(-2.0f, acc[mt][nt][3], c21);
                    int t0 = mt * 2, t1 = mt * 2 + 1;
                    if (s0 < sec[t0]) { if (s0 < best[t0]) { sec[t0] = best[t0]; best[t0] = s0; idx8[t0] = k0; } else sec[t0] = s0; }
                    if (s1 < sec[t0]) { if (s1 < best[t0]) { sec[t0] = best[t0]; best[t0] = s1; idx8[t0] = k0 + 1; } else sec[t0] = s1; }
                    if (s2 < sec[t1]) { if (s2 < best[t1]) { sec[t1] = best[t1]; best[t1] = s2; idx8[t1] = k0; } else sec[t1] = s2; }
                    if (s3 < sec[t1]) { if (s3 < best[t1]) { sec[t1] = best[t1]; best[t1] = s3; idx8[t1] = k0 + 1; } else sec[t1] = s3; }
                    acc[mt][nt][0] = 0.0f; acc[mt][nt][1] = 0.0f;
                    acc[mt][nt][2] = 0.0f; acc[mt][nt][3] = 0.0f;
                }
            }
        }

        __syncthreads();                       // all warps done reading buf sbuf
        if (q + 2 < 16) {
            int q2 = q + 2;
            load_cchunk(C, sb + (sbuf ? SM_B1 : SM_B0),
                        (q2 >> 2) * 128, (q2 & 3) * 64, tid);
            CP_COMMIT();
            CP_WAIT(1);                        // chunk q+1 ready
        } else if (q == 14) {
            CP_WAIT(0);                        // last chunk ready
        }
        if (q < 15) __syncthreads();
    }

    // quad merge (lanes differing in qcol share rows)
    #pragma unroll
    for (int t = 0; t < 8; ++t) {
        float b = best[t], s = sec[t];
        int   i = idx8[t];
        #pragma unroll
        for (int o = 1; o <= 2; o <<= 1) {
            float b2 = __shfl_xor_sync(0xFFFFFFFFu, b, o);
            float s2 = __shfl_xor_sync(0xFFFFFFFFu, s, o);
            int   i2 = __shfl_xor_sync(0xFFFFFFFFu, i, o);
            if (b2 < b || (b2 == b && i2 < i)) { s = fminf(b, s2); b = b2; i = i2; }
            else                               { s = fminf(s, b2); }
        }
        if (qcol == 0) {
            int row = RM + (t >> 1) * 16 + qrow + (t & 1) * 8;
            bvS[wn * 128 + row] = b;
            svS[wn * 128 + row] = s;
            ivS[wn * 128 + row] = i;
        }
    }
    __syncthreads();

    // final cross-warp merge + decision (one thread per point)
    if (tid < 128) {
        float bb = bvS[tid], ss = svS[tid];
        int   ii = ivS[tid];
        #pragma unroll
        for (int w = 1; w < 4; ++w) {
            float b2 = bvS[w * 128 + tid], s2 = svS[w * 128 + tid];
            int   i2 = ivS[w * 128 + tid];
            if (b2 < bb || (b2 == bb && i2 < ii)) { ss = fminf(bb, s2); bb = b2; ii = i2; }
            else                                   { ss = fminf(ss, b2); }
        }
        int n = n0 + tid;
        g_idx[n] = ii;
        int mark = ii;
        if (ss - bb < TAU) {
            int slot = atomicAdd(&g_nref, 1);
            g_rlist[slot] = n;
            mark = -1;                      // refine kernel writes the 1.0 later
        }
        ivS[tid] = mark;                    // reuse row 0 of IV as mark array
    }
    __syncthreads();

    // stream full one-hot rows (replaces global memset; overlaps with GEMM chip-wide)
    #pragma unroll
    for (int i = 0; i < 64; ++i) {
        int idx = i * 256 + tid;
        int row = idx >> 7, s = idx & 127;
        int m = ivS[row];
        float4 v = make_float4(0.f, 0.f, 0.f, 0.f);
        if ((m >> 2) == s) ((float*)&v)[m & 3] = 1.0f;
        __stcs((float4*)(out + (size_t)(n0 + row) * K_CL + s * 4), v);
    }
}

// ---------------------------------------------------------------------------
// refine: near-tie points -> all-K distances via Kahan fp32 dot, assembled with
// the reference's rounding order fl(fl(x2 - 2*dot) + c2); first-index tie-break.
// ---------------------------------------------------------------------------
__device__ __forceinline__ void kadd(float& s, float& comp, float t) {
    float y = __fsub_rn(t, comp);
    float u = __fadd_rn(s, y);
    comp = __fsub_rn(__fsub_rn(u, s), y);
    s = u;
}

__global__ __launch_bounds__(256)
void refine_kernel(const float* __restrict__ X, const float* __restrict__ C,
                   float* __restrict__ out) {
    __shared__ float  xsh[D_DIM];
    __shared__ double xwr[8];
    __shared__ float  x2sh;
    __shared__ float  rv[256];
    __shared__ int    ri[256];

    const int tid  = threadIdx.x;
    const int nref = g_nref;

    for (int it = blockIdx.x; it < nref; it += gridDim.x) {
        const int n = g_rlist[it];
        __syncthreads();
        xsh[tid] = X[(size_t)n * D_DIM + tid];
        __syncthreads();
        {
            double p = (double)xsh[tid] * (double)xsh[tid];
            #pragma unroll
            for (int o = 16; o >= 1; o >>= 1)
                p += __shfl_xor_sync(0xFFFFFFFFu, p, o);
            if ((tid & 31) == 0) xwr[tid >> 5] = p;
            __syncthreads();
            if (tid == 0) {
                double t = 0.0;
                #pragma unroll
                for (int w = 0; w < 8; ++w) t += xwr[w];
                x2sh = (float)t;
            }
            __syncthreads();
        }
        const float x2f = x2sh;
        const float4* xs4 = (const float4*)xsh;

        float bv = 3.4e38f;
        int   bi = 0x7fffffff;
        #pragma unroll
        for (int kk = 0; kk < 2; ++kk) {
            const int k = 2 * tid + kk;
            const float4* cp = (const float4*)(C + (size_t)k * D_DIM);
            float s = 0.0f, comp = 0.0f;
            #pragma unroll 4
            for (int j = 0; j < D_DIM / 4; ++j) {
                float4 cv = cp[j];
                float4 xv = xs4[j];
                kadd(s, comp, __fmul_rn(cv.x, xv.x));
                kadd(s, comp, __fmul_rn(cv.y, xv.y));
                kadd(s, comp, __fmul_rn(cv.z, xv.z));
                kadd(s, comp, __fmul_rn(cv.w, xv.w));
            }
            float dotf = __fadd_rn(s, comp);
            float m = __fmul_rn(2.0f, dotf);
            float a = __fsub_rn(x2f, m);
            float dist = __fadd_rn(a, g_c2[k]);
            if (dist < bv || (dist == bv && k < bi)) { bv = dist; bi = k; }
        }
        rv[tid] = bv; ri[tid] = bi;
        __syncthreads();
        #pragma unroll
        for (int st = 128; st > 0; st >>= 1) {
            if (tid < st) {
                float ov = rv[tid + st]; int oi = ri[tid + st];
                if (ov < rv[tid] || (ov == rv[tid] && oi < ri[tid])) {
                    rv[tid] = ov; ri[tid] = oi;
                }
            }
            __syncthreads();
        }
        if (tid == 0) {
            g_idx[n] = ri[0];
            out[(size_t)n * K_CL + ri[0]] = 1.0f;   // row already all-zero
        }
    }
}

// ---------------------------------------------------------------------------
// scatter-reduce into per-cluster sums + counts (one warp per point)
// ---------------------------------------------------------------------------
__global__ void accum_kernel(const float* __restrict__ X) {
    int gw   = (blockIdx.x * blockDim.x + threadIdx.x) >> 5;
    int lane = threadIdx.x & 31;
    if (gw >= N_TOT) return;
    int k = g_idx[gw];
    const float* x = X + (size_t)gw * D_DIM;
    float* s = g_sums + (size_t)k * D_DIM;
    #pragma unroll
    for (int j = 0; j < D_DIM / 32; ++j) {
        int d = lane + j * 32;
        atomicAdd(&s[d], x[d]);
    }
    if (lane == 0) atomicAdd(&g_counts[k], 1);
}

// ---------------------------------------------------------------------------
__global__ void finalize_kernel(const float* __restrict__ C, float* __restrict__ outc) {
    int t = blockIdx.x * blockDim.x + threadIdx.x;
    if (t >= K_CL * D_DIM) return;
    int k = t >> 8;
    float cnt = (float)g_counts[k];
    float nc  = g_sums[t] / cnt;
    outc[t] = fmaf(0.9f, C[t], 0.1f * nc);
}

// ---------------------------------------------------------------------------
extern "C" void kernel_launch(void* const* d_in, const int* in_sizes, int n_in,
                              void* d_out, int out_size) {
    const float* X = (const float*)d_in[0];
    const float* C = (const float*)d_in[1];
    float* out = (float*)d_out;
    (void)in_sizes; (void)n_in; (void)out_size;

    cudaFuncSetAttribute(argmin_mma, cudaFuncAttributeMaxDynamicSharedMemorySize,
                         SMEM_TOTAL);

    init_kernel<<<(K_CL * D_DIM + 255) / 256, 256>>>(C);
    argmin_mma<<<N_TOT / MT, 256, SMEM_TOTAL>>>(X, C, out);
    refine_kernel<<<1024, 256>>>(X, C, out);
    accum_kernel<<<(N_TOT * 32) / 256, 256>>>(X);
    finalize_kernel<<<(K_CL * D_DIM + 255) / 256, 256>>>(C, out + (size_t)N_TOT * K_CL);
}